// round 10
// baseline (speedup 1.0000x reference)
#include <cuda_runtime.h>
#include <math.h>

#define NLAYERS 4
#define DMODEL 1024
#define NHEADS 16
#define HDIM 64
#define FFDIM 4096
#define BATCH 2
#define SEQ 1024
#define MROWS (BATCH*SEQ)   // 2048

// ---------------- scratch (no allocations allowed) ----------------
__device__ float g_x [(size_t)MROWS*DMODEL];
__device__ float g_nb[(size_t)MROWS*DMODEL];
__device__ float g_qb[(size_t)MROWS*DMODEL];
__device__ float g_kb[(size_t)MROWS*DMODEL];
__device__ float g_vb[(size_t)MROWS*DMODEL];
__device__ float g_ab[(size_t)MROWS*DMODEL];
__device__ float g_t0b[(size_t)MROWS*FFDIM];
__device__ float g_t1b[(size_t)MROWS*FFDIM];
__device__ float g_biasb[NHEADS*SEQ];

// ---------------- TF32 helpers ----------------
__device__ __forceinline__ float f2tf(float f) {
    unsigned u;
    asm("cvt.rna.tf32.f32 %0, %1;" : "=r"(u) : "f"(f));
    return __uint_as_float(u);
}

__device__ __forceinline__ float4 f2tf4(float4 v) {
    v.x = f2tf(v.x); v.y = f2tf(v.y); v.z = f2tf(v.z); v.w = f2tf(v.w);
    return v;
}

__device__ __forceinline__ void mma_tf32(
    float* d, const unsigned* a, const unsigned* b)
{
    asm volatile(
        "mma.sync.aligned.m16n8k8.row.col.f32.tf32.tf32.f32 "
        "{%0,%1,%2,%3}, {%4,%5,%6,%7}, {%8,%9}, {%0,%1,%2,%3};"
        : "+f"(d[0]), "+f"(d[1]), "+f"(d[2]), "+f"(d[3])
        : "r"(a[0]), "r"(a[1]), "r"(a[2]), "r"(a[3]),
          "r"(b[0]), "r"(b[1]));
}

// ---------------- small utility kernels ----------------
__global__ void copy4_k(const float* __restrict__ src, float* __restrict__ dst, int n4) {
    int i = blockIdx.x * blockDim.x + threadIdx.x;
    if (i < n4) ((float4*)dst)[i] = ((const float4*)src)[i];
}

// bias table: tab[h*SEQ + delta] = rel_emb[bucket(delta)][h], delta = max(i-j,0)
__global__ void biastab_k(const float* __restrict__ emb, float* __restrict__ tab) {
    int idx = blockIdx.x * blockDim.x + threadIdx.x;
    if (idx >= NHEADS * SEQ) return;
    int h = idx / SEQ;
    int d = idx % SEQ;
    int bucket;
    if (d < 16) {
        bucket = d;
    } else {
        float l = logf((float)d / 16.0f) / logf(8.0f) * 16.0f;
        bucket = 16 + (int)l;
        if (bucket > 31) bucket = 31;
    }
    tab[h * SEQ + d] = emb[bucket * NHEADS + h];
}

// RMSNorm: one block per row of 1024
__global__ __launch_bounds__(256) void rmsnorm_k(
    const float* __restrict__ x, const float* __restrict__ g, float* __restrict__ o)
{
    __shared__ float sh[32];
    const int row = blockIdx.x;
    const float* xr = x + (size_t)row * DMODEL;
    const int t = threadIdx.x;
    float s = 0.f;
    for (int c = t; c < DMODEL; c += 256) { float v = xr[c]; s += v * v; }
#pragma unroll
    for (int off = 16; off > 0; off >>= 1) s += __shfl_xor_sync(0xffffffffu, s, off);
    if ((t & 31) == 0) sh[t >> 5] = s;
    __syncthreads();
    if (t < 32) {
        float v = (t < 8) ? sh[t] : 0.f;
#pragma unroll
        for (int off = 4; off > 0; off >>= 1) v += __shfl_xor_sync(0xffffffffu, v, off);
        if (t == 0) sh[0] = v;
    }
    __syncthreads();
    const float r = rsqrtf(sh[0] / (float)DMODEL + 1e-6f);
    float* orow = o + (size_t)row * DMODEL;
    for (int c = t; c < DMODEL; c += 256) orow[c] = g[c] * xr[c] * r;
}

// ---------------- batched dense GEMM (up to 3 problems via z) ----------------
// CTA tile 128x128, BK=16, 4 warps in 2x2, warp tile 64x64.
// A staged [row][k] stride 20; B staged [k][col] stride 136. Both conflict-free
// for staging stores AND fragment loads. Inputs tf32-rounded at staging.
struct GB {
    const float* A[3];
    const float* B[3];
    const float* R[3];
    float*       C[3];
};

__global__ __launch_bounds__(128) void mmT_k(
    GB gb, int N, int K, int lda, int ldb, int ldc)
{
    __shared__ __align__(16) float As[2][128][20];
    __shared__ __align__(16) float Bs[2][16][136];
    const int t = threadIdx.x;
    const int lane = t & 31, warp = t >> 5;
    const int z  = blockIdx.z;
    const int m0 = blockIdx.y * 128;
    const int n0 = blockIdx.x * 128;
    const int wm = (warp >> 1) * 64;
    const int wn = (warp & 1) * 64;
    const int gid = lane >> 2, tig = lane & 3;

    const float* Ap = gb.A[z] + (size_t)(m0 + t) * lda;        // one row/thread
    const float* Bp = gb.B[z] + n0 + 4 * lane;                  // col = 4*lane

    float acc[4][8][4];
#pragma unroll
    for (int i = 0; i < 4; i++)
#pragma unroll
        for (int j = 0; j < 8; j++)
#pragma unroll
            for (int r = 0; r < 4; r++) acc[i][j][r] = 0.f;

    float4 av[4], bv[4];
    // prologue: k0 = 0
#pragma unroll
    for (int i = 0; i < 4; i++) av[i] = *(const float4*)(Ap + 4 * i);
#pragma unroll
    for (int i = 0; i < 4; i++)
        bv[i] = *(const float4*)(Bp + (size_t)(warp + 4 * i) * ldb);
#pragma unroll
    for (int i = 0; i < 4; i++) *(float4*)&As[0][t][4 * i] = f2tf4(av[i]);
#pragma unroll
    for (int i = 0; i < 4; i++) *(float4*)&Bs[0][warp + 4 * i][4 * lane] = f2tf4(bv[i]);
    __syncthreads();

    int cur = 0;
    for (int k0 = 0; k0 < K; k0 += 16) {
        const bool last = (k0 + 16 >= K);
        if (!last) {
#pragma unroll
            for (int i = 0; i < 4; i++)
                av[i] = *(const float4*)(Ap + k0 + 16 + 4 * i);
#pragma unroll
            for (int i = 0; i < 4; i++)
                bv[i] = *(const float4*)(Bp + (size_t)(k0 + 16 + warp + 4 * i) * ldb);
        }
#pragma unroll
        for (int ks = 0; ks < 2; ks++) {
            const int kk = ks * 8;
            unsigned af[4][4], bf[8][2];
#pragma unroll
            for (int mt = 0; mt < 4; mt++) {
                const float* ar0 = &As[cur][wm + mt * 16 + gid    ][kk];
                const float* ar1 = &As[cur][wm + mt * 16 + gid + 8][kk];
                af[mt][0] = __float_as_uint(ar0[tig]);
                af[mt][1] = __float_as_uint(ar1[tig]);
                af[mt][2] = __float_as_uint(ar0[tig + 4]);
                af[mt][3] = __float_as_uint(ar1[tig + 4]);
            }
#pragma unroll
            for (int nt = 0; nt < 8; nt++) {
                const int c = wn + nt * 8 + gid;
                bf[nt][0] = __float_as_uint(Bs[cur][kk + tig    ][c]);
                bf[nt][1] = __float_as_uint(Bs[cur][kk + tig + 4][c]);
            }
#pragma unroll
            for (int mt = 0; mt < 4; mt++)
#pragma unroll
                for (int nt = 0; nt < 8; nt++)
                    mma_tf32(acc[mt][nt], af[mt], bf[nt]);
        }
        if (!last) {
            const int nxt = cur ^ 1;
#pragma unroll
            for (int i = 0; i < 4; i++) *(float4*)&As[nxt][t][4 * i] = f2tf4(av[i]);
#pragma unroll
            for (int i = 0; i < 4; i++)
                *(float4*)&Bs[nxt][warp + 4 * i][4 * lane] = f2tf4(bv[i]);
            __syncthreads();
            cur = nxt;
        }
    }

    // epilogue
    const float* R = gb.R[z];
    float* C = gb.C[z];
#pragma unroll
    for (int mt = 0; mt < 4; mt++) {
        const int r = m0 + wm + mt * 16 + gid;
#pragma unroll
        for (int nt = 0; nt < 8; nt++) {
            const int c = n0 + wn + nt * 8 + 2 * tig;
            const size_t o0 = (size_t)r * ldc + c;
            const size_t o1 = (size_t)(r + 8) * ldc + c;
            float v0 = acc[mt][nt][0], v1 = acc[mt][nt][1];
            float v2 = acc[mt][nt][2], v3 = acc[mt][nt][3];
            if (R) { v0 += R[o0]; v1 += R[o0+1]; v2 += R[o1]; v3 += R[o1+1]; }
            C[o0] = v0; C[o0+1] = v1; C[o1] = v2; C[o1+1] = v3;
        }
    }
}

// ---------------- flash attention ----------------
// grid (1, SEQ/64, B*H), block 128 (4 warps).
__global__ __launch_bounds__(128) void flash_k(
    const float* __restrict__ Q, const float* __restrict__ Kv,
    const float* __restrict__ V, float* __restrict__ O,
    const float* __restrict__ biasTab, const float* __restrict__ mask,
    int selfMode)
{
    __shared__ __align__(16) float KV[64][72];
    __shared__ __align__(16) float Ps[64][72];
    __shared__ float sscale[64];
    __shared__ float sl[64];

    const int bh = blockIdx.z, b = bh >> 4, h = bh & 15;
    const int i0 = blockIdx.y * 64;
    const int t = threadIdx.x, lane = t & 31, warp = t >> 5;
    const int gid = lane >> 2, tig = lane & 3;
    const int wr = warp * 16;
    const int wn = warp * 16;
    const int sr = t >> 1, sc = (t & 1) * 32;

    unsigned aq[8][4];
    {
        const float* q0 = Q + (size_t)(b * SEQ + i0 + wr + gid) * DMODEL + h * HDIM;
        const float* q1 = q0 + 8 * DMODEL;
#pragma unroll
        for (int k8 = 0; k8 < 8; k8++) {
            const int k = k8 * 8;
            aq[k8][0] = __float_as_uint(f2tf(q0[k + tig]));
            aq[k8][1] = __float_as_uint(f2tf(q1[k + tig]));
            aq[k8][2] = __float_as_uint(f2tf(q0[k + tig + 4]));
            aq[k8][3] = __float_as_uint(f2tf(q1[k + tig + 4]));
        }
    }

    float m_run[2] = {-3.0e38f, -3.0e38f};
    float l_run[2] = {0.f, 0.f};
    float acc_o[4][2][4];
#pragma unroll
    for (int mt = 0; mt < 4; mt++)
#pragma unroll
        for (int nt = 0; nt < 2; nt++)
#pragma unroll
            for (int e = 0; e < 4; e++) acc_o[mt][nt][e] = 0.f;

    const float* kbase = Kv + (size_t)b * SEQ * DMODEL + h * HDIM;
    const float* vbase = V  + (size_t)b * SEQ * DMODEL + h * HDIM;
    const int nj = selfMode ? (i0 / 64 + 1) : (SEQ / 64);

    for (int jt = 0; jt < nj; jt++) {
        const int j0 = jt * 64;
        __syncthreads();
        {
            const float* kp = kbase + (size_t)(j0 + sr) * DMODEL + sc;
#pragma unroll
            for (int u = 0; u < 8; u++) {
                float4 v4 = *(const float4*)(kp + u * 4);
                KV[sc+u*4+0][sr] = f2tf(v4.x);
                KV[sc+u*4+1][sr] = f2tf(v4.y);
                KV[sc+u*4+2][sr] = f2tf(v4.z);
                KV[sc+u*4+3][sr] = f2tf(v4.w);
            }
        }
        __syncthreads();
        float s[8][4];
#pragma unroll
        for (int nt = 0; nt < 8; nt++)
#pragma unroll
            for (int e = 0; e < 4; e++) s[nt][e] = 0.f;
#pragma unroll
        for (int k8 = 0; k8 < 8; k8++) {
            const int k = k8 * 8;
            unsigned bf[8][2];
#pragma unroll
            for (int nt = 0; nt < 8; nt++) {
                bf[nt][0] = __float_as_uint(KV[k+tig  ][nt*8+gid]);
                bf[nt][1] = __float_as_uint(KV[k+tig+4][nt*8+gid]);
            }
#pragma unroll
            for (int nt = 0; nt < 8; nt++)
                mma_tf32(s[nt], aq[k8], bf[nt]);
        }
        float pm[2] = {-3.0e38f, -3.0e38f};
        const int gi0 = i0 + wr + gid;
#pragma unroll
        for (int nt = 0; nt < 8; nt++) {
#pragma unroll
            for (int e = 0; e < 4; e++) {
                const int gi = gi0 + (e >> 1) * 8;
                const int gj = j0 + nt * 8 + 2 * tig + (e & 1);
                float v = s[nt][e];
                if (selfMode) {
                    int dd = gi - gj; if (dd < 0) dd = 0;
                    v += biasTab[h * SEQ + dd]
                       + mask[(size_t)b * SEQ * SEQ + (size_t)gi * SEQ + gj];
                } else {
                    v += mask[(size_t)b * SEQ + gj];
                }
                s[nt][e] = v;
                pm[e >> 1] = fmaxf(pm[e >> 1], v);
            }
        }
#pragma unroll
        for (int i = 0; i < 2; i++) {
            pm[i] = fmaxf(pm[i], __shfl_xor_sync(0xffffffffu, pm[i], 1));
            pm[i] = fmaxf(pm[i], __shfl_xor_sync(0xffffffffu, pm[i], 2));
        }
        float mnew[2], scl[2], psum[2] = {0.f, 0.f};
#pragma unroll
        for (int i = 0; i < 2; i++) {
            mnew[i] = fmaxf(m_run[i], pm[i]);
            scl[i]  = __expf(m_run[i] - mnew[i]);
        }
#pragma unroll
        for (int nt = 0; nt < 8; nt++)
#pragma unroll
            for (int e = 0; e < 4; e++) {
                float p = __expf(s[nt][e] - mnew[e >> 1]);
                s[nt][e] = p;
                psum[e >> 1] += p;
            }
#pragma unroll
        for (int i = 0; i < 2; i++) {
            psum[i] += __shfl_xor_sync(0xffffffffu, psum[i], 1);
            psum[i] += __shfl_xor_sync(0xffffffffu, psum[i], 2);
            l_run[i] = l_run[i] * scl[i] + psum[i];
            m_run[i] = mnew[i];
        }
        if (tig == 0) {
            sscale[wr + gid]     = scl[0];
            sscale[wr + gid + 8] = scl[1];
        }
#pragma unroll
        for (int nt = 0; nt < 8; nt++)
#pragma unroll
            for (int e = 0; e < 4; e++)
                Ps[nt*8 + 2*tig + (e & 1)][wr + gid + (e >> 1) * 8] = f2tf(s[nt][e]);
        __syncthreads();
        {
            const float* vp = vbase + (size_t)(j0 + sr) * DMODEL + sc;
#pragma unroll
            for (int u = 0; u < 8; u++) {
                float4 v4 = *(const float4*)(vp + u * 4);
                *(float4*)&KV[sr][sc + u * 4] = f2tf4(v4);
            }
        }
        float rs[4][2];
#pragma unroll
        for (int mt = 0; mt < 4; mt++) {
            rs[mt][0] = sscale[mt * 16 + gid];
            rs[mt][1] = sscale[mt * 16 + gid + 8];
        }
#pragma unroll
        for (int mt = 0; mt < 4; mt++)
#pragma unroll
            for (int nt = 0; nt < 2; nt++)
#pragma unroll
                for (int e = 0; e < 4; e++)
                    acc_o[mt][nt][e] *= rs[mt][e >> 1];
        __syncthreads();
#pragma unroll
        for (int k8 = 0; k8 < 8; k8++) {
            const int k = k8 * 8;
            unsigned af[4][4], bf[2][2];
#pragma unroll
            for (int mt = 0; mt < 4; mt++) {
                af[mt][0] = __float_as_uint(Ps[k+tig  ][mt*16+gid]);
                af[mt][1] = __float_as_uint(Ps[k+tig  ][mt*16+gid+8]);
                af[mt][2] = __float_as_uint(Ps[k+tig+4][mt*16+gid]);
                af[mt][3] = __float_as_uint(Ps[k+tig+4][mt*16+gid+8]);
            }
#pragma unroll
            for (int nt = 0; nt < 2; nt++) {
                bf[nt][0] = __float_as_uint(KV[k+tig  ][wn+nt*8+gid]);
                bf[nt][1] = __float_as_uint(KV[k+tig+4][wn+nt*8+gid]);
            }
#pragma unroll
            for (int mt = 0; mt < 4; mt++)
#pragma unroll
                for (int nt = 0; nt < 2; nt++)
                    mma_tf32(acc_o[mt][nt], af[mt], bf[nt]);
        }
    }
    if (tig == 0) {
        sl[wr + gid]     = l_run[0];
        sl[wr + gid + 8] = l_run[1];
    }
    __syncthreads();
#pragma unroll
    for (int mt = 0; mt < 4; mt++) {
        const float inv0 = 1.0f / sl[mt * 16 + gid];
        const float inv1 = 1.0f / sl[mt * 16 + gid + 8];
        const int r0 = i0 + mt * 16 + gid;
#pragma unroll
        for (int nt = 0; nt < 2; nt++) {
            const int c = h * HDIM + wn + nt * 8 + 2 * tig;
            const size_t o0 = (size_t)(b * SEQ + r0) * DMODEL + c;
            const size_t o1 = o0 + (size_t)8 * DMODEL;
            O[o0]     = acc_o[mt][nt][0] * inv0;
            O[o0 + 1] = acc_o[mt][nt][1] * inv0;
            O[o1]     = acc_o[mt][nt][2] * inv1;
            O[o1 + 1] = acc_o[mt][nt][3] * inv1;
        }
    }
}

// ---------------- GeGLU combine (float4): t0 = gelu_exact(t0) * t1 ----------
__global__ void geglu_k(float4* __restrict__ t0, const float4* __restrict__ t1, int n4) {
    int i = blockIdx.x * blockDim.x + threadIdx.x;
    if (i < n4) {
        float4 x = t0[i];
        float4 y = t1[i];
        const float c = 0.70710678118654752f;
        x.x = 0.5f * x.x * (1.0f + erff(x.x * c)) * y.x;
        x.y = 0.5f * x.y * (1.0f + erff(x.y * c)) * y.y;
        x.z = 0.5f * x.z * (1.0f + erff(x.z * c)) * y.z;
        x.w = 0.5f * x.w * (1.0f + erff(x.w * c)) * y.w;
        t0[i] = x;
    }
}

// ---------------- host orchestration ----------------
extern "C" void kernel_launch(void* const* d_in, const int* in_sizes, int n_in,
                              void* d_out, int out_size)
{
    const float* hs    = (const float*)d_in[0];
    const float* enc   = (const float*)d_in[1];
    const float* amask = (const float*)d_in[2];
    const float* emask = (const float*)d_in[3];
    const float* Wq_s  = (const float*)d_in[4];
    const float* Wk_s  = (const float*)d_in[5];
    const float* Wv_s  = (const float*)d_in[6];
    const float* Wo_s  = (const float*)d_in[7];
    const float* Wq_c  = (const float*)d_in[8];
    const float* Wk_c  = (const float*)d_in[9];
    const float* Wv_c  = (const float*)d_in[10];
    const float* Wo_c  = (const float*)d_in[11];
    const float* Wi0   = (const float*)d_in[12];
    const float* Wi1   = (const float*)d_in[13];
    const float* Wof   = (const float*)d_in[14];
    const float* g1    = (const float*)d_in[15];
    const float* g2    = (const float*)d_in[16];
    const float* g3    = (const float*)d_in[17];
    const float* gf    = (const float*)d_in[18];
    const float* remb  = (const float*)d_in[19];

    static float *px = nullptr, *pn, *pq, *pk, *pv, *pa, *pt0, *pt1, *pb;
    if (!px) {
        cudaGetSymbolAddress((void**)&px,  g_x);
        cudaGetSymbolAddress((void**)&pn,  g_nb);
        cudaGetSymbolAddress((void**)&pq,  g_qb);
        cudaGetSymbolAddress((void**)&pk,  g_kb);
        cudaGetSymbolAddress((void**)&pv,  g_vb);
        cudaGetSymbolAddress((void**)&pa,  g_ab);
        cudaGetSymbolAddress((void**)&pt0, g_t0b);
        cudaGetSymbolAddress((void**)&pt1, g_t1b);
        cudaGetSymbolAddress((void**)&pb,  g_biasb);
    }

    const dim3 gD3(DMODEL / 128, MROWS / 128, 3);   // batched QKV  (8,16,3)
    const dim3 gD1(DMODEL / 128, MROWS / 128, 1);   // single D-GEMM
    const dim3 gF2(FFDIM / 128,  MROWS / 128, 2);   // batched Wi0/Wi1 (32,16,2)
    const dim3 gFl(1, SEQ / 64, BATCH * NHEADS);    // flash attention

    copy4_k<<<(MROWS * DMODEL / 4 + 255) / 256, 256>>>(hs, px, MROWS * DMODEL / 4);
    biastab_k<<<(NHEADS * SEQ + 255) / 256, 256>>>(remb, pb);

    for (int i = 0; i < NLAYERS; i++) {
        const size_t oD = (size_t)i * DMODEL * DMODEL;
        const size_t oF = (size_t)i * DMODEL * FFDIM;
        // --- causal self-attention with rel-pos bias ---
        rmsnorm_k<<<MROWS, 256>>>(px, g1 + i * DMODEL, pn);
        {
            GB gb = {};
            gb.A[0] = pn; gb.A[1] = pn; gb.A[2] = pn;
            gb.B[0] = Wq_s + oD; gb.B[1] = Wk_s + oD; gb.B[2] = Wv_s + oD;
            gb.C[0] = pq; gb.C[1] = pk; gb.C[2] = pv;
            mmT_k<<<gD3, 128>>>(gb, DMODEL, DMODEL, DMODEL, DMODEL, DMODEL);
        }
        flash_k<<<gFl, 128>>>(pq, pk, pv, pa, pb, amask, 1);
        {
            GB gb = {};
            gb.A[0] = pa; gb.B[0] = Wo_s + oD; gb.R[0] = px; gb.C[0] = px;
            mmT_k<<<gD1, 128>>>(gb, DMODEL, DMODEL, DMODEL, DMODEL, DMODEL);
        }
        // --- cross-attention ---
        rmsnorm_k<<<MROWS, 256>>>(px, g2 + i * DMODEL, pn);
        {
            GB gb = {};
            gb.A[0] = pn; gb.A[1] = enc; gb.A[2] = enc;
            gb.B[0] = Wq_c + oD; gb.B[1] = Wk_c + oD; gb.B[2] = Wv_c + oD;
            gb.C[0] = pq; gb.C[1] = pk; gb.C[2] = pv;
            mmT_k<<<gD3, 128>>>(gb, DMODEL, DMODEL, DMODEL, DMODEL, DMODEL);
        }
        flash_k<<<gFl, 128>>>(pq, pk, pv, pa, pb, emask, 0);
        {
            GB gb = {};
            gb.A[0] = pa; gb.B[0] = Wo_c + oD; gb.R[0] = px; gb.C[0] = px;
            mmT_k<<<gD1, 128>>>(gb, DMODEL, DMODEL, DMODEL, DMODEL, DMODEL);
        }
        // --- GeGLU FFN ---
        rmsnorm_k<<<MROWS, 256>>>(px, g3 + i * DMODEL, pn);
        {
            GB gb = {};
            gb.A[0] = pn; gb.A[1] = pn;
            gb.B[0] = Wi0 + oF; gb.B[1] = Wi1 + oF;
            gb.C[0] = pt0; gb.C[1] = pt1;
            mmT_k<<<gF2, 128>>>(gb, FFDIM, DMODEL, DMODEL, FFDIM, FFDIM);
        }
        geglu_k<<<(MROWS * FFDIM / 4 + 255) / 256, 256>>>(
            (float4*)pt0, (const float4*)pt1, MROWS * FFDIM / 4);
        {
            GB gb = {};
            gb.A[0] = pt0; gb.B[0] = Wof + (size_t)i * FFDIM * DMODEL;
            gb.R[0] = px; gb.C[0] = px;
            mmT_k<<<gD1, 128>>>(gb, DMODEL, FFDIM, FFDIM, DMODEL, DMODEL);
        }
    }
    rmsnorm_k<<<MROWS, 256>>>(px, gf, (float*)d_out);
}

// round 12
// speedup vs baseline: 1.0039x; 1.0039x over previous
#include <cuda_runtime.h>
#include <math.h>

#define NLAYERS 4
#define DMODEL 1024
#define NHEADS 16
#define HDIM 64
#define FFDIM 4096
#define BATCH 2
#define SEQ 1024
#define MROWS (BATCH*SEQ)   // 2048

// ---------------- scratch (no allocations allowed) ----------------
__device__ float g_x [(size_t)MROWS*DMODEL];
__device__ float g_nb[(size_t)MROWS*DMODEL];
__device__ float g_qb[(size_t)MROWS*DMODEL];
__device__ float g_kb[(size_t)MROWS*DMODEL];
__device__ float g_vb[(size_t)MROWS*DMODEL];
__device__ float g_ab[(size_t)MROWS*DMODEL];
__device__ float g_t0b[(size_t)MROWS*FFDIM];
__device__ float g_t1b[(size_t)MROWS*FFDIM];
__device__ float g_biasb[NHEADS*SEQ];

// ---------------- TF32 helpers ----------------
__device__ __forceinline__ float f2tf(float f) {
    unsigned u;
    asm("cvt.rna.tf32.f32 %0, %1;" : "=r"(u) : "f"(f));
    return __uint_as_float(u);
}

__device__ __forceinline__ float4 f2tf4(float4 v) {
    v.x = f2tf(v.x); v.y = f2tf(v.y); v.z = f2tf(v.z); v.w = f2tf(v.w);
    return v;
}

__device__ __forceinline__ void mma_tf32(
    float* d, const unsigned* a, const unsigned* b)
{
    asm volatile(
        "mma.sync.aligned.m16n8k8.row.col.f32.tf32.tf32.f32 "
        "{%0,%1,%2,%3}, {%4,%5,%6,%7}, {%8,%9}, {%0,%1,%2,%3};"
        : "+f"(d[0]), "+f"(d[1]), "+f"(d[2]), "+f"(d[3])
        : "r"(a[0]), "r"(a[1]), "r"(a[2]), "r"(a[3]),
          "r"(b[0]), "r"(b[1]));
}

// ---------------- small utility kernels ----------------
__global__ void copy4_k(const float* __restrict__ src, float* __restrict__ dst, int n4) {
    int i = blockIdx.x * blockDim.x + threadIdx.x;
    if (i < n4) ((float4*)dst)[i] = ((const float4*)src)[i];
}

// bias table: tab[h*SEQ + delta] = rel_emb[bucket(delta)][h], delta = max(i-j,0)
__global__ void biastab_k(const float* __restrict__ emb, float* __restrict__ tab) {
    int idx = blockIdx.x * blockDim.x + threadIdx.x;
    if (idx >= NHEADS * SEQ) return;
    int h = idx / SEQ;
    int d = idx % SEQ;
    int bucket;
    if (d < 16) {
        bucket = d;
    } else {
        float l = logf((float)d / 16.0f) / logf(8.0f) * 16.0f;
        bucket = 16 + (int)l;
        if (bucket > 31) bucket = 31;
    }
    tab[h * SEQ + d] = emb[bucket * NHEADS + h];
}

// RMSNorm: one block per row of 1024
__global__ __launch_bounds__(256) void rmsnorm_k(
    const float* __restrict__ x, const float* __restrict__ g, float* __restrict__ o)
{
    __shared__ float sh[32];
    const int row = blockIdx.x;
    const float* xr = x + (size_t)row * DMODEL;
    const int t = threadIdx.x;
    float s = 0.f;
    for (int c = t; c < DMODEL; c += 256) { float v = xr[c]; s += v * v; }
#pragma unroll
    for (int off = 16; off > 0; off >>= 1) s += __shfl_xor_sync(0xffffffffu, s, off);
    if ((t & 31) == 0) sh[t >> 5] = s;
    __syncthreads();
    if (t < 32) {
        float v = (t < 8) ? sh[t] : 0.f;
#pragma unroll
        for (int off = 4; off > 0; off >>= 1) v += __shfl_xor_sync(0xffffffffu, v, off);
        if (t == 0) sh[0] = v;
    }
    __syncthreads();
    const float r = rsqrtf(sh[0] / (float)DMODEL + 1e-6f);
    float* orow = o + (size_t)row * DMODEL;
    for (int c = t; c < DMODEL; c += 256) orow[c] = g[c] * xr[c] * r;
}

// ---------------- batched dense GEMM (up to 3 problems via z) ----------------
// CTA tile 128x128, BK=16, 4 warps in 2x2, warp tile 64x64.
// A staged [row][k] stride 20; B staged [k][col] stride 136. Both conflict-free
// for staging stores AND fragment loads. Inputs tf32-rounded at staging.
struct GB {
    const float* A[3];
    const float* B[3];
    const float* R[3];
    float*       C[3];
};

__global__ __launch_bounds__(128) void mmT_k(
    GB gb, int N, int K, int lda, int ldb, int ldc)
{
    __shared__ __align__(16) float As[2][128][20];
    __shared__ __align__(16) float Bs[2][16][136];
    const int t = threadIdx.x;
    const int lane = t & 31, warp = t >> 5;
    const int z  = blockIdx.z;
    const int m0 = blockIdx.y * 128;
    const int n0 = blockIdx.x * 128;
    const int wm = (warp >> 1) * 64;
    const int wn = (warp & 1) * 64;
    const int gid = lane >> 2, tig = lane & 3;

    const float* Ap = gb.A[z] + (size_t)(m0 + t) * lda;        // one row/thread
    const float* Bp = gb.B[z] + n0 + 4 * lane;                  // col = 4*lane

    float acc[4][8][4];
#pragma unroll
    for (int i = 0; i < 4; i++)
#pragma unroll
        for (int j = 0; j < 8; j++)
#pragma unroll
            for (int r = 0; r < 4; r++) acc[i][j][r] = 0.f;

    float4 av[4], bv[4];
    // prologue: k0 = 0
#pragma unroll
    for (int i = 0; i < 4; i++) av[i] = *(const float4*)(Ap + 4 * i);
#pragma unroll
    for (int i = 0; i < 4; i++)
        bv[i] = *(const float4*)(Bp + (size_t)(warp + 4 * i) * ldb);
#pragma unroll
    for (int i = 0; i < 4; i++) *(float4*)&As[0][t][4 * i] = f2tf4(av[i]);
#pragma unroll
    for (int i = 0; i < 4; i++) *(float4*)&Bs[0][warp + 4 * i][4 * lane] = f2tf4(bv[i]);
    __syncthreads();

    int cur = 0;
    for (int k0 = 0; k0 < K; k0 += 16) {
        const bool last = (k0 + 16 >= K);
        if (!last) {
#pragma unroll
            for (int i = 0; i < 4; i++)
                av[i] = *(const float4*)(Ap + k0 + 16 + 4 * i);
#pragma unroll
            for (int i = 0; i < 4; i++)
                bv[i] = *(const float4*)(Bp + (size_t)(k0 + 16 + warp + 4 * i) * ldb);
        }
#pragma unroll
        for (int ks = 0; ks < 2; ks++) {
            const int kk = ks * 8;
            unsigned af[4][4], bf[8][2];
#pragma unroll
            for (int mt = 0; mt < 4; mt++) {
                const float* ar0 = &As[cur][wm + mt * 16 + gid    ][kk];
                const float* ar1 = &As[cur][wm + mt * 16 + gid + 8][kk];
                af[mt][0] = __float_as_uint(ar0[tig]);
                af[mt][1] = __float_as_uint(ar1[tig]);
                af[mt][2] = __float_as_uint(ar0[tig + 4]);
                af[mt][3] = __float_as_uint(ar1[tig + 4]);
            }
#pragma unroll
            for (int nt = 0; nt < 8; nt++) {
                const int c = wn + nt * 8 + gid;
                bf[nt][0] = __float_as_uint(Bs[cur][kk + tig    ][c]);
                bf[nt][1] = __float_as_uint(Bs[cur][kk + tig + 4][c]);
            }
#pragma unroll
            for (int mt = 0; mt < 4; mt++)
#pragma unroll
                for (int nt = 0; nt < 8; nt++)
                    mma_tf32(acc[mt][nt], af[mt], bf[nt]);
        }
        if (!last) {
            const int nxt = cur ^ 1;
#pragma unroll
            for (int i = 0; i < 4; i++) *(float4*)&As[nxt][t][4 * i] = f2tf4(av[i]);
#pragma unroll
            for (int i = 0; i < 4; i++)
                *(float4*)&Bs[nxt][warp + 4 * i][4 * lane] = f2tf4(bv[i]);
            __syncthreads();
            cur = nxt;
        }
    }

    // epilogue
    const float* R = gb.R[z];
    float* C = gb.C[z];
#pragma unroll
    for (int mt = 0; mt < 4; mt++) {
        const int r = m0 + wm + mt * 16 + gid;
#pragma unroll
        for (int nt = 0; nt < 8; nt++) {
            const int c = n0 + wn + nt * 8 + 2 * tig;
            const size_t o0 = (size_t)r * ldc + c;
            const size_t o1 = (size_t)(r + 8) * ldc + c;
            float v0 = acc[mt][nt][0], v1 = acc[mt][nt][1];
            float v2 = acc[mt][nt][2], v3 = acc[mt][nt][3];
            if (R) { v0 += R[o0]; v1 += R[o0+1]; v2 += R[o1]; v3 += R[o1+1]; }
            C[o0] = v0; C[o0+1] = v1; C[o1] = v2; C[o1+1] = v3;
        }
    }
}

// ---------------- flash attention ----------------
// grid (1, SEQ/64, B*H), block 128 (4 warps).
__global__ __launch_bounds__(128) void flash_k(
    const float* __restrict__ Q, const float* __restrict__ Kv,
    const float* __restrict__ V, float* __restrict__ O,
    const float* __restrict__ biasTab, const float* __restrict__ mask,
    int selfMode)
{
    __shared__ __align__(16) float KV[64][72];
    __shared__ __align__(16) float Ps[64][72];
    __shared__ float sscale[64];
    __shared__ float sl[64];

    const int bh = blockIdx.z, b = bh >> 4, h = bh & 15;
    const int i0 = blockIdx.y * 64;
    const int t = threadIdx.x, lane = t & 31, warp = t >> 5;
    const int gid = lane >> 2, tig = lane & 3;
    const int wr = warp * 16;
    const int wn = warp * 16;
    const int sr = t >> 1, sc = (t & 1) * 32;

    unsigned aq[8][4];
    {
        const float* q0 = Q + (size_t)(b * SEQ + i0 + wr + gid) * DMODEL + h * HDIM;
        const float* q1 = q0 + 8 * DMODEL;
#pragma unroll
        for (int k8 = 0; k8 < 8; k8++) {
            const int k = k8 * 8;
            aq[k8][0] = __float_as_uint(f2tf(q0[k + tig]));
            aq[k8][1] = __float_as_uint(f2tf(q1[k + tig]));
            aq[k8][2] = __float_as_uint(f2tf(q0[k + tig + 4]));
            aq[k8][3] = __float_as_uint(f2tf(q1[k + tig + 4]));
        }
    }

    float m_run[2] = {-3.0e38f, -3.0e38f};
    float l_run[2] = {0.f, 0.f};
    float acc_o[4][2][4];
#pragma unroll
    for (int mt = 0; mt < 4; mt++)
#pragma unroll
        for (int nt = 0; nt < 2; nt++)
#pragma unroll
            for (int e = 0; e < 4; e++) acc_o[mt][nt][e] = 0.f;

    const float* kbase = Kv + (size_t)b * SEQ * DMODEL + h * HDIM;
    const float* vbase = V  + (size_t)b * SEQ * DMODEL + h * HDIM;
    const int nj = selfMode ? (i0 / 64 + 1) : (SEQ / 64);

    for (int jt = 0; jt < nj; jt++) {
        const int j0 = jt * 64;
        __syncthreads();
        {
            const float* kp = kbase + (size_t)(j0 + sr) * DMODEL + sc;
#pragma unroll
            for (int u = 0; u < 8; u++) {
                float4 v4 = *(const float4*)(kp + u * 4);
                KV[sc+u*4+0][sr] = f2tf(v4.x);
                KV[sc+u*4+1][sr] = f2tf(v4.y);
                KV[sc+u*4+2][sr] = f2tf(v4.z);
                KV[sc+u*4+3][sr] = f2tf(v4.w);
            }
        }
        __syncthreads();
        float s[8][4];
#pragma unroll
        for (int nt = 0; nt < 8; nt++)
#pragma unroll
            for (int e = 0; e < 4; e++) s[nt][e] = 0.f;
#pragma unroll
        for (int k8 = 0; k8 < 8; k8++) {
            const int k = k8 * 8;
            unsigned bf[8][2];
#pragma unroll
            for (int nt = 0; nt < 8; nt++) {
                bf[nt][0] = __float_as_uint(KV[k+tig  ][nt*8+gid]);
                bf[nt][1] = __float_as_uint(KV[k+tig+4][nt*8+gid]);
            }
#pragma unroll
            for (int nt = 0; nt < 8; nt++)
                mma_tf32(s[nt], aq[k8], bf[nt]);
        }
        float pm[2] = {-3.0e38f, -3.0e38f};
        const int gi0 = i0 + wr + gid;
#pragma unroll
        for (int nt = 0; nt < 8; nt++) {
#pragma unroll
            for (int e = 0; e < 4; e++) {
                const int gi = gi0 + (e >> 1) * 8;
                const int gj = j0 + nt * 8 + 2 * tig + (e & 1);
                float v = s[nt][e];
                if (selfMode) {
                    int dd = gi - gj; if (dd < 0) dd = 0;
                    v += biasTab[h * SEQ + dd]
                       + mask[(size_t)b * SEQ * SEQ + (size_t)gi * SEQ + gj];
                } else {
                    v += mask[(size_t)b * SEQ + gj];
                }
                s[nt][e] = v;
                pm[e >> 1] = fmaxf(pm[e >> 1], v);
            }
        }
#pragma unroll
        for (int i = 0; i < 2; i++) {
            pm[i] = fmaxf(pm[i], __shfl_xor_sync(0xffffffffu, pm[i], 1));
            pm[i] = fmaxf(pm[i], __shfl_xor_sync(0xffffffffu, pm[i], 2));
        }
        float mnew[2], scl[2], psum[2] = {0.f, 0.f};
#pragma unroll
        for (int i = 0; i < 2; i++) {
            mnew[i] = fmaxf(m_run[i], pm[i]);
            scl[i]  = __expf(m_run[i] - mnew[i]);
        }
#pragma unroll
        for (int nt = 0; nt < 8; nt++)
#pragma unroll
            for (int e = 0; e < 4; e++) {
                float p = __expf(s[nt][e] - mnew[e >> 1]);
                s[nt][e] = p;
                psum[e >> 1] += p;
            }
#pragma unroll
        for (int i = 0; i < 2; i++) {
            psum[i] += __shfl_xor_sync(0xffffffffu, psum[i], 1);
            psum[i] += __shfl_xor_sync(0xffffffffu, psum[i], 2);
            l_run[i] = l_run[i] * scl[i] + psum[i];
            m_run[i] = mnew[i];
        }
        if (tig == 0) {
            sscale[wr + gid]     = scl[0];
            sscale[wr + gid + 8] = scl[1];
        }
#pragma unroll
        for (int nt = 0; nt < 8; nt++)
#pragma unroll
            for (int e = 0; e < 4; e++)
                Ps[nt*8 + 2*tig + (e & 1)][wr + gid + (e >> 1) * 8] = f2tf(s[nt][e]);
        __syncthreads();
        {
            const float* vp = vbase + (size_t)(j0 + sr) * DMODEL + sc;
#pragma unroll
            for (int u = 0; u < 8; u++) {
                float4 v4 = *(const float4*)(vp + u * 4);
                *(float4*)&KV[sr][sc + u * 4] = f2tf4(v4);
            }
        }
        float rs[4][2];
#pragma unroll
        for (int mt = 0; mt < 4; mt++) {
            rs[mt][0] = sscale[mt * 16 + gid];
            rs[mt][1] = sscale[mt * 16 + gid + 8];
        }
#pragma unroll
        for (int mt = 0; mt < 4; mt++)
#pragma unroll
            for (int nt = 0; nt < 2; nt++)
#pragma unroll
                for (int e = 0; e < 4; e++)
                    acc_o[mt][nt][e] *= rs[mt][e >> 1];
        __syncthreads();
#pragma unroll
        for (int k8 = 0; k8 < 8; k8++) {
            const int k = k8 * 8;
            unsigned af[4][4], bf[2][2];
#pragma unroll
            for (int mt = 0; mt < 4; mt++) {
                af[mt][0] = __float_as_uint(Ps[k+tig  ][mt*16+gid]);
                af[mt][1] = __float_as_uint(Ps[k+tig  ][mt*16+gid+8]);
                af[mt][2] = __float_as_uint(Ps[k+tig+4][mt*16+gid]);
                af[mt][3] = __float_as_uint(Ps[k+tig+4][mt*16+gid+8]);
            }
#pragma unroll
            for (int nt = 0; nt < 2; nt++) {
                bf[nt][0] = __float_as_uint(KV[k+tig  ][wn+nt*8+gid]);
                bf[nt][1] = __float_as_uint(KV[k+tig+4][wn+nt*8+gid]);
            }
#pragma unroll
            for (int mt = 0; mt < 4; mt++)
#pragma unroll
                for (int nt = 0; nt < 2; nt++)
                    mma_tf32(acc_o[mt][nt], af[mt], bf[nt]);
        }
    }
    if (tig == 0) {
        sl[wr + gid]     = l_run[0];
        sl[wr + gid + 8] = l_run[1];
    }
    __syncthreads();
#pragma unroll
    for (int mt = 0; mt < 4; mt++) {
        const float inv0 = 1.0f / sl[mt * 16 + gid];
        const float inv1 = 1.0f / sl[mt * 16 + gid + 8];
        const int r0 = i0 + mt * 16 + gid;
#pragma unroll
        for (int nt = 0; nt < 2; nt++) {
            const int c = h * HDIM + wn + nt * 8 + 2 * tig;
            const size_t o0 = (size_t)(b * SEQ + r0) * DMODEL + c;
            const size_t o1 = o0 + (size_t)8 * DMODEL;
            O[o0]     = acc_o[mt][nt][0] * inv0;
            O[o0 + 1] = acc_o[mt][nt][1] * inv0;
            O[o1]     = acc_o[mt][nt][2] * inv1;
            O[o1 + 1] = acc_o[mt][nt][3] * inv1;
        }
    }
}

// ---------------- GeGLU combine (float4): t0 = gelu_exact(t0) * t1 ----------
__global__ void geglu_k(float4* __restrict__ t0, const float4* __restrict__ t1, int n4) {
    int i = blockIdx.x * blockDim.x + threadIdx.x;
    if (i < n4) {
        float4 x = t0[i];
        float4 y = t1[i];
        const float c = 0.70710678118654752f;
        x.x = 0.5f * x.x * (1.0f + erff(x.x * c)) * y.x;
        x.y = 0.5f * x.y * (1.0f + erff(x.y * c)) * y.y;
        x.z = 0.5f * x.z * (1.0f + erff(x.z * c)) * y.z;
        x.w = 0.5f * x.w * (1.0f + erff(x.w * c)) * y.w;
        t0[i] = x;
    }
}

// ---------------- host orchestration ----------------
extern "C" void kernel_launch(void* const* d_in, const int* in_sizes, int n_in,
                              void* d_out, int out_size)
{
    const float* hs    = (const float*)d_in[0];
    const float* enc   = (const float*)d_in[1];
    const float* amask = (const float*)d_in[2];
    const float* emask = (const float*)d_in[3];
    const float* Wq_s  = (const float*)d_in[4];
    const float* Wk_s  = (const float*)d_in[5];
    const float* Wv_s  = (const float*)d_in[6];
    const float* Wo_s  = (const float*)d_in[7];
    const float* Wq_c  = (const float*)d_in[8];
    const float* Wk_c  = (const float*)d_in[9];
    const float* Wv_c  = (const float*)d_in[10];
    const float* Wo_c  = (const float*)d_in[11];
    const float* Wi0   = (const float*)d_in[12];
    const float* Wi1   = (const float*)d_in[13];
    const float* Wof   = (const float*)d_in[14];
    const float* g1    = (const float*)d_in[15];
    const float* g2    = (const float*)d_in[16];
    const float* g3    = (const float*)d_in[17];
    const float* gf    = (const float*)d_in[18];
    const float* remb  = (const float*)d_in[19];

    static float *px = nullptr, *pn, *pq, *pk, *pv, *pa, *pt0, *pt1, *pb;
    if (!px) {
        cudaGetSymbolAddress((void**)&px,  g_x);
        cudaGetSymbolAddress((void**)&pn,  g_nb);
        cudaGetSymbolAddress((void**)&pq,  g_qb);
        cudaGetSymbolAddress((void**)&pk,  g_kb);
        cudaGetSymbolAddress((void**)&pv,  g_vb);
        cudaGetSymbolAddress((void**)&pa,  g_ab);
        cudaGetSymbolAddress((void**)&pt0, g_t0b);
        cudaGetSymbolAddress((void**)&pt1, g_t1b);
        cudaGetSymbolAddress((void**)&pb,  g_biasb);
    }

    const dim3 gD3(DMODEL / 128, MROWS / 128, 3);   // batched QKV  (8,16,3)
    const dim3 gD1(DMODEL / 128, MROWS / 128, 1);   // single D-GEMM
    const dim3 gF2(FFDIM / 128,  MROWS / 128, 2);   // batched Wi0/Wi1 (32,16,2)
    const dim3 gFl(1, SEQ / 64, BATCH * NHEADS);    // flash attention

    copy4_k<<<(MROWS * DMODEL / 4 + 255) / 256, 256>>>(hs, px, MROWS * DMODEL / 4);
    biastab_k<<<(NHEADS * SEQ + 255) / 256, 256>>>(remb, pb);

    for (int i = 0; i < NLAYERS; i++) {
        const size_t oD = (size_t)i * DMODEL * DMODEL;
        const size_t oF = (size_t)i * DMODEL * FFDIM;
        // --- causal self-attention with rel-pos bias ---
        rmsnorm_k<<<MROWS, 256>>>(px, g1 + i * DMODEL, pn);
        {
            GB gb = {};
            gb.A[0] = pn; gb.A[1] = pn; gb.A[2] = pn;
            gb.B[0] = Wq_s + oD; gb.B[1] = Wk_s + oD; gb.B[2] = Wv_s + oD;
            gb.C[0] = pq; gb.C[1] = pk; gb.C[2] = pv;
            mmT_k<<<gD3, 128>>>(gb, DMODEL, DMODEL, DMODEL, DMODEL, DMODEL);
        }
        flash_k<<<gFl, 128>>>(pq, pk, pv, pa, pb, amask, 1);
        {
            GB gb = {};
            gb.A[0] = pa; gb.B[0] = Wo_s + oD; gb.R[0] = px; gb.C[0] = px;
            mmT_k<<<gD1, 128>>>(gb, DMODEL, DMODEL, DMODEL, DMODEL, DMODEL);
        }
        // --- cross-attention ---
        rmsnorm_k<<<MROWS, 256>>>(px, g2 + i * DMODEL, pn);
        {
            GB gb = {};
            gb.A[0] = pn; gb.A[1] = enc; gb.A[2] = enc;
            gb.B[0] = Wq_c + oD; gb.B[1] = Wk_c + oD; gb.B[2] = Wv_c + oD;
            gb.C[0] = pq; gb.C[1] = pk; gb.C[2] = pv;
            mmT_k<<<gD3, 128>>>(gb, DMODEL, DMODEL, DMODEL, DMODEL, DMODEL);
        }
        flash_k<<<gFl, 128>>>(pq, pk, pv, pa, pb, emask, 0);
        {
            GB gb = {};
            gb.A[0] = pa; gb.B[0] = Wo_c + oD; gb.R[0] = px; gb.C[0] = px;
            mmT_k<<<gD1, 128>>>(gb, DMODEL, DMODEL, DMODEL, DMODEL, DMODEL);
        }
        // --- GeGLU FFN ---
        rmsnorm_k<<<MROWS, 256>>>(px, g3 + i * DMODEL, pn);
        {
            GB gb = {};
            gb.A[0] = pn; gb.A[1] = pn;
            gb.B[0] = Wi0 + oF; gb.B[1] = Wi1 + oF;
            gb.C[0] = pt0; gb.C[1] = pt1;
            mmT_k<<<gF2, 128>>>(gb, FFDIM, DMODEL, DMODEL, FFDIM, FFDIM);
        }
        geglu_k<<<(MROWS * FFDIM / 4 + 255) / 256, 256>>>(
            (float4*)pt0, (const float4*)pt1, MROWS * FFDIM / 4);
        {
            GB gb = {};
            gb.A[0] = pt0; gb.B[0] = Wof + (size_t)i * FFDIM * DMODEL;
            gb.R[0] = px; gb.C[0] = px;
            mmT_k<<<gD1, 128>>>(gb, DMODEL, FFDIM, FFDIM, DMODEL, DMODEL);
        }
    }
    rmsnorm_k<<<MROWS, 256>>>(px, gf, (float*)d_out);
}

// round 17
// speedup vs baseline: 1.1409x; 1.1365x over previous
#include <cuda_runtime.h>
#include <stdint.h>
#include <math.h>

typedef unsigned int u32;

#define NLAYERS 4
#define DMODEL 1024
#define NHEADS 16
#define HDIM 64
#define FFDIM 4096
#define BATCH 2
#define SEQ 1024
#define MROWS (BATCH*SEQ)   // 2048
#define LSZ ((size_t)MROWS*DMODEL)

// ---------------- scratch (no allocations allowed) ----------------
__device__ float g_x [LSZ];
__device__ float g_nb[LSZ];
__device__ float g_qb[LSZ];
__device__ float g_kb[LSZ];
__device__ float g_vb[LSZ];
__device__ float g_ab[LSZ];
__device__ float g_t0b[(size_t)MROWS*FFDIM];
__device__ float g_t1b[(size_t)MROWS*FFDIM];
__device__ float g_biasb[NHEADS*SEQ];
__device__ float g_ekb[(size_t)NLAYERS*LSZ];   // enc K per layer (32 MB)
__device__ float g_evb[(size_t)NLAYERS*LSZ];   // enc V per layer (32 MB)

// ---------------- TF32 helpers ----------------
__device__ __forceinline__ float f2tf(float f) {
    u32 u;
    asm("cvt.rna.tf32.f32 %0, %1;" : "=r"(u) : "f"(f));
    return __uint_as_float(u);
}
__device__ __forceinline__ float4 f2tf4(float4 v) {
    v.x = f2tf(v.x); v.y = f2tf(v.y); v.z = f2tf(v.z); v.w = f2tf(v.w);
    return v;
}
__device__ __forceinline__ void mma_tf32(float* d, const u32* a, const u32* b) {
    asm volatile(
        "mma.sync.aligned.m16n8k8.row.col.f32.tf32.tf32.f32 "
        "{%0,%1,%2,%3}, {%4,%5,%6,%7}, {%8,%9}, {%0,%1,%2,%3};"
        : "+f"(d[0]), "+f"(d[1]), "+f"(d[2]), "+f"(d[3])
        : "r"(a[0]), "r"(a[1]), "r"(a[2]), "r"(a[3]), "r"(b[0]), "r"(b[1]));
}

// ---------------- small utility kernels ----------------
__global__ void copy4_k(const float* __restrict__ src, float* __restrict__ dst, int n4) {
    int i = blockIdx.x * blockDim.x + threadIdx.x;
    if (i < n4) ((float4*)dst)[i] = ((const float4*)src)[i];
}

__global__ void biastab_k(const float* __restrict__ emb, float* __restrict__ tab) {
    int idx = blockIdx.x * blockDim.x + threadIdx.x;
    if (idx >= NHEADS * SEQ) return;
    int h = idx / SEQ;
    int d = idx % SEQ;
    int bucket;
    if (d < 16) {
        bucket = d;
    } else {
        float l = logf((float)d / 16.0f) / logf(8.0f) * 16.0f;
        bucket = 16 + (int)l;
        if (bucket > 31) bucket = 31;
    }
    tab[h * SEQ + d] = emb[bucket * NHEADS + h];
}

__global__ __launch_bounds__(256) void rmsnorm_k(
    const float* __restrict__ x, const float* __restrict__ g, float* __restrict__ o)
{
    __shared__ float sh[32];
    const int row = blockIdx.x;
    const float* xr = x + (size_t)row * DMODEL;
    const int t = threadIdx.x;
    float s = 0.f;
    for (int c = t; c < DMODEL; c += 256) { float v = xr[c]; s += v * v; }
#pragma unroll
    for (int off = 16; off > 0; off >>= 1) s += __shfl_xor_sync(0xffffffffu, s, off);
    if ((t & 31) == 0) sh[t >> 5] = s;
    __syncthreads();
    if (t < 32) {
        float v = (t < 8) ? sh[t] : 0.f;
#pragma unroll
        for (int off = 4; off > 0; off >>= 1) v += __shfl_xor_sync(0xffffffffu, v, off);
        if (t == 0) sh[0] = v;
    }
    __syncthreads();
    const float r = rsqrtf(sh[0] / (float)DMODEL + 1e-6f);
    float* orow = o + (size_t)row * DMODEL;
    for (int c = t; c < DMODEL; c += 256) orow[c] = g[c] * xr[c] * r;
}

// ---------------- TF32 MMA GEMM core (rounds inputs at staging) ----------------
// CTA tile 64 x 128, BK=16, 4 warps, warp tile 64 x 32.
__device__ __forceinline__ void mm_core128(
    const float* __restrict__ A, int lda,
    const float* __restrict__ B, int ldb,
    int K, float acc[4][4][4])
{
    __shared__ __align__(16) float As[2][16][72];
    __shared__ __align__(16) float Bs[2][16][136];
    const int t = threadIdx.x;
    const int lane = t & 31, warp = t >> 5;
    const int wn  = warp * 32;
    const int gid = lane >> 2, tig = lane & 3;

    const int aRow = t >> 1, aK = (t & 1) * 8;
    const float* Ap = A + (size_t)aRow * lda + aK;
    const int bRow = t >> 5, bCol = (t & 31) * 4;
    const float* Bp = B + bCol;

    float4 a0, a1, bv0, bv1, bv2, bv3;
    a0 = *(const float4*)(Ap);
    a1 = *(const float4*)(Ap + 4);
    bv0 = *(const float4*)(Bp + (size_t)(bRow     ) * ldb);
    bv1 = *(const float4*)(Bp + (size_t)(bRow +  4) * ldb);
    bv2 = *(const float4*)(Bp + (size_t)(bRow +  8) * ldb);
    bv3 = *(const float4*)(Bp + (size_t)(bRow + 12) * ldb);
    {
        As[0][aK+0][aRow]=f2tf(a0.x); As[0][aK+1][aRow]=f2tf(a0.y);
        As[0][aK+2][aRow]=f2tf(a0.z); As[0][aK+3][aRow]=f2tf(a0.w);
        As[0][aK+4][aRow]=f2tf(a1.x); As[0][aK+5][aRow]=f2tf(a1.y);
        As[0][aK+6][aRow]=f2tf(a1.z); As[0][aK+7][aRow]=f2tf(a1.w);
        *(float4*)&Bs[0][bRow   ][bCol] = f2tf4(bv0);
        *(float4*)&Bs[0][bRow+ 4][bCol] = f2tf4(bv1);
        *(float4*)&Bs[0][bRow+ 8][bCol] = f2tf4(bv2);
        *(float4*)&Bs[0][bRow+12][bCol] = f2tf4(bv3);
    }
    __syncthreads();

    int cur = 0;
    for (int k0 = 0; k0 < K; k0 += 16) {
        const bool last = (k0 + 16 >= K);
        if (!last) {
            a0 = *(const float4*)(Ap + k0 + 16);
            a1 = *(const float4*)(Ap + k0 + 20);
            const float* Bn = Bp + (size_t)(k0 + 16) * ldb;
            bv0 = *(const float4*)(Bn + (size_t)(bRow     ) * ldb);
            bv1 = *(const float4*)(Bn + (size_t)(bRow +  4) * ldb);
            bv2 = *(const float4*)(Bn + (size_t)(bRow +  8) * ldb);
            bv3 = *(const float4*)(Bn + (size_t)(bRow + 12) * ldb);
        }
#pragma unroll
        for (int ks = 0; ks < 2; ks++) {
            const int kk = ks * 8;
            u32 af[4][4], bf[4][2];
#pragma unroll
            for (int mt = 0; mt < 4; mt++) {
                const int r = mt * 16 + gid;
                af[mt][0] = __float_as_uint(As[cur][kk+tig  ][r]);
                af[mt][1] = __float_as_uint(As[cur][kk+tig  ][r+8]);
                af[mt][2] = __float_as_uint(As[cur][kk+tig+4][r]);
                af[mt][3] = __float_as_uint(As[cur][kk+tig+4][r+8]);
            }
#pragma unroll
            for (int nt = 0; nt < 4; nt++) {
                const int c = wn + nt * 8 + gid;
                bf[nt][0] = __float_as_uint(Bs[cur][kk+tig  ][c]);
                bf[nt][1] = __float_as_uint(Bs[cur][kk+tig+4][c]);
            }
#pragma unroll
            for (int mt = 0; mt < 4; mt++)
#pragma unroll
                for (int nt = 0; nt < 4; nt++)
                    mma_tf32(acc[mt][nt], af[mt], bf[nt]);
        }
        if (!last) {
            const int nxt = cur ^ 1;
            As[nxt][aK+0][aRow]=f2tf(a0.x); As[nxt][aK+1][aRow]=f2tf(a0.y);
            As[nxt][aK+2][aRow]=f2tf(a0.z); As[nxt][aK+3][aRow]=f2tf(a0.w);
            As[nxt][aK+4][aRow]=f2tf(a1.x); As[nxt][aK+5][aRow]=f2tf(a1.y);
            As[nxt][aK+6][aRow]=f2tf(a1.z); As[nxt][aK+7][aRow]=f2tf(a1.w);
            *(float4*)&Bs[nxt][bRow   ][bCol] = f2tf4(bv0);
            *(float4*)&Bs[nxt][bRow+ 4][bCol] = f2tf4(bv1);
            *(float4*)&Bs[nxt][bRow+ 8][bCol] = f2tf4(bv2);
            *(float4*)&Bs[nxt][bRow+12][bCol] = f2tf4(bv3);
            __syncthreads();
            cur = nxt;
        }
    }
}

// ---------------- batched dense GEMM (up to 8 problems via z) ----------------
struct GB {
    const float* A[8];
    const float* B[8];
    const float* R[8];
    float*       C[8];
};

__global__ __launch_bounds__(128) void mmT_k(
    GB gb, int N, int K, int lda, int ldb, int ldc)
{
    const int z  = blockIdx.z;
    const int m0 = blockIdx.y * 64;
    const int n0 = blockIdx.x * 128;
    const float* A = gb.A[z] + (size_t)m0 * lda;
    const float* B = gb.B[z] + n0;
    float acc[4][4][4];
#pragma unroll
    for (int i = 0; i < 4; i++)
#pragma unroll
        for (int j = 0; j < 4; j++)
#pragma unroll
            for (int r = 0; r < 4; r++) acc[i][j][r] = 0.f;

    mm_core128(A, lda, B, ldb, K, acc);

    const int t = threadIdx.x, lane = t & 31, warp = t >> 5;
    const int gid = lane >> 2, tig = lane & 3;
    const int wn = warp * 32;
    const float* R = gb.R[z];
    float* C = gb.C[z];
#pragma unroll
    for (int mt = 0; mt < 4; mt++) {
        const int r = m0 + mt * 16 + gid;
#pragma unroll
        for (int nt = 0; nt < 4; nt++) {
            const int c = n0 + wn + nt * 8 + 2 * tig;
            const size_t o0 = (size_t)r * ldc + c;
            const size_t o1 = (size_t)(r + 8) * ldc + c;
            float v0 = acc[mt][nt][0], v1 = acc[mt][nt][1];
            float v2 = acc[mt][nt][2], v3 = acc[mt][nt][3];
            if (R) { v0 += R[o0]; v1 += R[o0+1]; v2 += R[o1]; v3 += R[o1+1]; }
            C[o0] = v0; C[o0+1] = v1; C[o1] = v2; C[o1+1] = v3;
        }
    }
}

// ---------------- flash attention ----------------
// grid (1, SEQ/64, B*H), block 128 (4 warps).
__global__ __launch_bounds__(128) void flash_k(
    const float* __restrict__ Q, const float* __restrict__ Kv,
    const float* __restrict__ V, float* __restrict__ O,
    const float* __restrict__ biasTab, const float* __restrict__ mask,
    int selfMode)
{
    __shared__ __align__(16) float KV[64][72];
    __shared__ __align__(16) float Ps[64][72];
    __shared__ float sscale[64];
    __shared__ float sl[64];

    const int bh = blockIdx.z, b = bh >> 4, h = bh & 15;
    const int i0 = blockIdx.y * 64;
    const int t = threadIdx.x, lane = t & 31, warp = t >> 5;
    const int gid = lane >> 2, tig = lane & 3;
    const int wr = warp * 16;
    const int wn = warp * 16;
    const int sr = t >> 1, sc = (t & 1) * 32;

    u32 aq[8][4];
    {
        const float* q0 = Q + (size_t)(b * SEQ + i0 + wr + gid) * DMODEL + h * HDIM;
        const float* q1 = q0 + 8 * DMODEL;
#pragma unroll
        for (int k8 = 0; k8 < 8; k8++) {
            const int k = k8 * 8;
            aq[k8][0] = __float_as_uint(f2tf(q0[k + tig]));
            aq[k8][1] = __float_as_uint(f2tf(q1[k + tig]));
            aq[k8][2] = __float_as_uint(f2tf(q0[k + tig + 4]));
            aq[k8][3] = __float_as_uint(f2tf(q1[k + tig + 4]));
        }
    }

    float m_run[2] = {-3.0e38f, -3.0e38f};
    float l_run[2] = {0.f, 0.f};
    float acc_o[4][2][4];
#pragma unroll
    for (int mt = 0; mt < 4; mt++)
#pragma unroll
        for (int nt = 0; nt < 2; nt++)
#pragma unroll
            for (int e = 0; e < 4; e++) acc_o[mt][nt][e] = 0.f;

    const float* kbase = Kv + (size_t)b * SEQ * DMODEL + h * HDIM;
    const float* vbase = V  + (size_t)b * SEQ * DMODEL + h * HDIM;
    const int nj = selfMode ? (i0 / 64 + 1) : (SEQ / 64);

    for (int jt = 0; jt < nj; jt++) {
        const int j0 = jt * 64;
        __syncthreads();
        {
            const float* kp = kbase + (size_t)(j0 + sr) * DMODEL + sc;
#pragma unroll
            for (int u = 0; u < 8; u++) {
                float4 v4 = *(const float4*)(kp + u * 4);
                KV[sc+u*4+0][sr] = f2tf(v4.x);
                KV[sc+u*4+1][sr] = f2tf(v4.y);
                KV[sc+u*4+2][sr] = f2tf(v4.z);
                KV[sc+u*4+3][sr] = f2tf(v4.w);
            }
        }
        __syncthreads();
        float s[8][4];
#pragma unroll
        for (int nt = 0; nt < 8; nt++)
#pragma unroll
            for (int e = 0; e < 4; e++) s[nt][e] = 0.f;
#pragma unroll
        for (int k8 = 0; k8 < 8; k8++) {
            const int k = k8 * 8;
            u32 bf[8][2];
#pragma unroll
            for (int nt = 0; nt < 8; nt++) {
                bf[nt][0] = __float_as_uint(KV[k+tig  ][nt*8+gid]);
                bf[nt][1] = __float_as_uint(KV[k+tig+4][nt*8+gid]);
            }
#pragma unroll
            for (int nt = 0; nt < 8; nt++)
                mma_tf32(s[nt], aq[k8], bf[nt]);
        }
        float pm[2] = {-3.0e38f, -3.0e38f};
        const int gi0 = i0 + wr + gid;
#pragma unroll
        for (int nt = 0; nt < 8; nt++) {
#pragma unroll
            for (int e = 0; e < 4; e++) {
                const int gi = gi0 + (e >> 1) * 8;
                const int gj = j0 + nt * 8 + 2 * tig + (e & 1);
                float v = s[nt][e];
                if (selfMode) {
                    int dd = gi - gj; if (dd < 0) dd = 0;
                    v += biasTab[h * SEQ + dd]
                       + mask[(size_t)b * SEQ * SEQ + (size_t)gi * SEQ + gj];
                } else {
                    v += mask[(size_t)b * SEQ + gj];
                }
                s[nt][e] = v;
                pm[e >> 1] = fmaxf(pm[e >> 1], v);
            }
        }
#pragma unroll
        for (int i = 0; i < 2; i++) {
            pm[i] = fmaxf(pm[i], __shfl_xor_sync(0xffffffffu, pm[i], 1));
            pm[i] = fmaxf(pm[i], __shfl_xor_sync(0xffffffffu, pm[i], 2));
        }
        float mnew[2], scl[2], psum[2] = {0.f, 0.f};
#pragma unroll
        for (int i = 0; i < 2; i++) {
            mnew[i] = fmaxf(m_run[i], pm[i]);
            scl[i]  = __expf(m_run[i] - mnew[i]);
        }
#pragma unroll
        for (int nt = 0; nt < 8; nt++)
#pragma unroll
            for (int e = 0; e < 4; e++) {
                float p = __expf(s[nt][e] - mnew[e >> 1]);
                s[nt][e] = p;
                psum[e >> 1] += p;
            }
#pragma unroll
        for (int i = 0; i < 2; i++) {
            psum[i] += __shfl_xor_sync(0xffffffffu, psum[i], 1);
            psum[i] += __shfl_xor_sync(0xffffffffu, psum[i], 2);
            l_run[i] = l_run[i] * scl[i] + psum[i];
            m_run[i] = mnew[i];
        }
        if (tig == 0) {
            sscale[wr + gid]     = scl[0];
            sscale[wr + gid + 8] = scl[1];
        }
#pragma unroll
        for (int nt = 0; nt < 8; nt++)
#pragma unroll
            for (int e = 0; e < 4; e++)
                Ps[nt*8 + 2*tig + (e & 1)][wr + gid + (e >> 1) * 8] = f2tf(s[nt][e]);
        __syncthreads();
        {
            const float* vp = vbase + (size_t)(j0 + sr) * DMODEL + sc;
#pragma unroll
            for (int u = 0; u < 8; u++)
                *(float4*)&KV[sr][sc + u * 4] = f2tf4(*(const float4*)(vp + u * 4));
        }
        float rs[4][2];
#pragma unroll
        for (int mt = 0; mt < 4; mt++) {
            rs[mt][0] = sscale[mt * 16 + gid];
            rs[mt][1] = sscale[mt * 16 + gid + 8];
        }
#pragma unroll
        for (int mt = 0; mt < 4; mt++)
#pragma unroll
            for (int nt = 0; nt < 2; nt++)
#pragma unroll
                for (int e = 0; e < 4; e++)
                    acc_o[mt][nt][e] *= rs[mt][e >> 1];
        __syncthreads();
#pragma unroll
        for (int k8 = 0; k8 < 8; k8++) {
            const int k = k8 * 8;
            u32 af[4][4], bf[2][2];
#pragma unroll
            for (int mt = 0; mt < 4; mt++) {
                af[mt][0] = __float_as_uint(Ps[k+tig  ][mt*16+gid]);
                af[mt][1] = __float_as_uint(Ps[k+tig  ][mt*16+gid+8]);
                af[mt][2] = __float_as_uint(Ps[k+tig+4][mt*16+gid]);
                af[mt][3] = __float_as_uint(Ps[k+tig+4][mt*16+gid+8]);
            }
#pragma unroll
            for (int nt = 0; nt < 2; nt++) {
                bf[nt][0] = __float_as_uint(KV[k+tig  ][wn+nt*8+gid]);
                bf[nt][1] = __float_as_uint(KV[k+tig+4][wn+nt*8+gid]);
            }
#pragma unroll
            for (int mt = 0; mt < 4; mt++)
#pragma unroll
                for (int nt = 0; nt < 2; nt++)
                    mma_tf32(acc_o[mt][nt], af[mt], bf[nt]);
        }
    }
    if (tig == 0) {
        sl[wr + gid]     = l_run[0];
        sl[wr + gid + 8] = l_run[1];
    }
    __syncthreads();
#pragma unroll
    for (int mt = 0; mt < 4; mt++) {
        const float inv0 = 1.0f / sl[mt * 16 + gid];
        const float inv1 = 1.0f / sl[mt * 16 + gid + 8];
        const int r0 = i0 + mt * 16 + gid;
#pragma unroll
        for (int nt = 0; nt < 2; nt++) {
            const int c = h * HDIM + wn + nt * 8 + 2 * tig;
            const size_t o0 = (size_t)(b * SEQ + r0) * DMODEL + c;
            const size_t o1 = o0 + (size_t)8 * DMODEL;
            O[o0]     = acc_o[mt][nt][0] * inv0;
            O[o0 + 1] = acc_o[mt][nt][1] * inv0;
            O[o1]     = acc_o[mt][nt][2] * inv1;
            O[o1 + 1] = acc_o[mt][nt][3] * inv1;
        }
    }
}

// ---------------- GeGLU combine (float4): t0 = gelu_exact(t0) * t1 ----------
__global__ void geglu_k(float4* __restrict__ t0, const float4* __restrict__ t1, int n4) {
    int i = blockIdx.x * blockDim.x + threadIdx.x;
    if (i < n4) {
        float4 x = t0[i];
        float4 y = t1[i];
        const float c = 0.70710678118654752f;
        x.x = 0.5f * x.x * (1.0f + erff(x.x * c)) * y.x;
        x.y = 0.5f * x.y * (1.0f + erff(x.y * c)) * y.y;
        x.z = 0.5f * x.z * (1.0f + erff(x.z * c)) * y.z;
        x.w = 0.5f * x.w * (1.0f + erff(x.w * c)) * y.w;
        t0[i] = x;
    }
}

// ---------------- host orchestration ----------------
extern "C" void kernel_launch(void* const* d_in, const int* in_sizes, int n_in,
                              void* d_out, int out_size)
{
    const float* hs    = (const float*)d_in[0];
    const float* enc   = (const float*)d_in[1];
    const float* amask = (const float*)d_in[2];
    const float* emask = (const float*)d_in[3];
    const float* Wq_s  = (const float*)d_in[4];
    const float* Wk_s  = (const float*)d_in[5];
    const float* Wv_s  = (const float*)d_in[6];
    const float* Wo_s  = (const float*)d_in[7];
    const float* Wq_c  = (const float*)d_in[8];
    const float* Wk_c  = (const float*)d_in[9];
    const float* Wv_c  = (const float*)d_in[10];
    const float* Wo_c  = (const float*)d_in[11];
    const float* Wi0   = (const float*)d_in[12];
    const float* Wi1   = (const float*)d_in[13];
    const float* Wof   = (const float*)d_in[14];
    const float* g1    = (const float*)d_in[15];
    const float* g2    = (const float*)d_in[16];
    const float* g3    = (const float*)d_in[17];
    const float* gf    = (const float*)d_in[18];
    const float* remb  = (const float*)d_in[19];

    static float *px = nullptr, *pn, *pq, *pk, *pv, *pa, *pt0, *pt1, *pb, *pek, *pev;
    static cudaStream_t s1 = nullptr;
    static cudaEvent_t evF = nullptr, evE = nullptr;
    if (!px) {
        cudaGetSymbolAddress((void**)&px,  g_x);
        cudaGetSymbolAddress((void**)&pn,  g_nb);
        cudaGetSymbolAddress((void**)&pq,  g_qb);
        cudaGetSymbolAddress((void**)&pk,  g_kb);
        cudaGetSymbolAddress((void**)&pv,  g_vb);
        cudaGetSymbolAddress((void**)&pa,  g_ab);
        cudaGetSymbolAddress((void**)&pt0, g_t0b);
        cudaGetSymbolAddress((void**)&pt1, g_t1b);
        cudaGetSymbolAddress((void**)&pb,  g_biasb);
        cudaGetSymbolAddress((void**)&pek, g_ekb);
        cudaGetSymbolAddress((void**)&pev, g_evb);
        cudaStreamCreateWithFlags(&s1, cudaStreamNonBlocking);
        cudaEventCreateWithFlags(&evF, cudaEventDisableTiming);
        cudaEventCreateWithFlags(&evE, cudaEventDisableTiming);
    }

    const dim3 gD3(8, 32, 3);                       // batched self QKV
    const dim3 gD1(8, 32, 1);                       // single D-GEMM
    const dim3 gF2(32, 32, 2);                      // batched Wi0/Wi1
    const dim3 gW (8, 32, 1);                       // Wof
    const dim3 gE (8, 32, 8);                       // all enc K/V (4 layers x 2)
    const dim3 gFl(1, SEQ / 64, BATCH * NHEADS);    // flash attention

    copy4_k<<<(MROWS * DMODEL / 4 + 255) / 256, 256>>>(hs, px, MROWS * DMODEL / 4);
    biastab_k<<<(NHEADS * SEQ + 255) / 256, 256>>>(remb, pb);

    // ---- fork: all encoder K/V projections for all layers on side stream ----
    cudaEventRecord(evF, 0);
    cudaStreamWaitEvent(s1, evF, 0);
    {
        GB g = {};
        for (int l = 0; l < NLAYERS; l++) {
            const size_t oD = (size_t)l * DMODEL * DMODEL;
            g.A[2*l]   = enc; g.B[2*l]   = Wk_c + oD; g.C[2*l]   = pek + (size_t)l * LSZ;
            g.A[2*l+1] = enc; g.B[2*l+1] = Wv_c + oD; g.C[2*l+1] = pev + (size_t)l * LSZ;
        }
        mmT_k<<<gE, 128, 0, s1>>>(g, DMODEL, DMODEL, DMODEL, DMODEL, DMODEL);
    }
    cudaEventRecord(evE, s1);

    for (int i = 0; i < NLAYERS; i++) {
        const size_t oD = (size_t)i * DMODEL * DMODEL;
        const size_t oF = (size_t)i * DMODEL * FFDIM;
        // --- causal self-attention with rel-pos bias ---
        rmsnorm_k<<<MROWS, 256>>>(px, g1 + i * DMODEL, pn);
        {
            GB g = {};
            g.A[0] = pn; g.A[1] = pn; g.A[2] = pn;
            g.B[0] = Wq_s + oD; g.B[1] = Wk_s + oD; g.B[2] = Wv_s + oD;
            g.C[0] = pq; g.C[1] = pk; g.C[2] = pv;
            mmT_k<<<gD3, 128>>>(g, DMODEL, DMODEL, DMODEL, DMODEL, DMODEL);
        }
        flash_k<<<gFl, 128>>>(pq, pk, pv, pa, pb, amask, 1);
        {
            GB g = {};
            g.A[0] = pa; g.B[0] = Wo_s + oD; g.R[0] = px; g.C[0] = px;
            mmT_k<<<gD1, 128>>>(g, DMODEL, DMODEL, DMODEL, DMODEL, DMODEL);
        }
        // --- cross-attention (enc K/V precomputed on side stream) ---
        rmsnorm_k<<<MROWS, 256>>>(px, g2 + i * DMODEL, pn);
        {
            GB g = {};
            g.A[0] = pn; g.B[0] = Wq_c + oD; g.C[0] = pq;
            mmT_k<<<gD1, 128>>>(g, DMODEL, DMODEL, DMODEL, DMODEL, DMODEL);
        }
        if (i == 0) cudaStreamWaitEvent(0, evE, 0);  // join side stream once
        flash_k<<<gFl, 128>>>(pq, pek + (size_t)i * LSZ, pev + (size_t)i * LSZ,
                              pa, pb, emask, 0);
        {
            GB g = {};
            g.A[0] = pa; g.B[0] = Wo_c + oD; g.R[0] = px; g.C[0] = px;
            mmT_k<<<gD1, 128>>>(g, DMODEL, DMODEL, DMODEL, DMODEL, DMODEL);
        }
        // --- GeGLU FFN ---
        rmsnorm_k<<<MROWS, 256>>>(px, g3 + i * DMODEL, pn);
        {
            GB g = {};
            g.A[0] = pn; g.A[1] = pn;
            g.B[0] = Wi0 + oF; g.B[1] = Wi1 + oF;
            g.C[0] = pt0; g.C[1] = pt1;
            mmT_k<<<gF2, 128>>>(g, FFDIM, DMODEL, DMODEL, FFDIM, FFDIM);
        }
        geglu_k<<<(MROWS * FFDIM / 4 + 255) / 256, 256>>>(
            (float4*)pt0, (const float4*)pt1, MROWS * FFDIM / 4);
        {
            GB g = {};
            g.A[0] = pt0; g.B[0] = Wof + (size_t)i * FFDIM * DMODEL;
            g.R[0] = px; g.C[0] = px;
            mmT_k<<<gW, 128>>>(g, DMODEL, FFDIM, FFDIM, DMODEL, DMODEL);
        }
    }
    rmsnorm_k<<<MROWS, 256>>>(px, gf, (float*)d_out);
}